// round 2
// baseline (speedup 1.0000x reference)
#include <cuda_runtime.h>
#include <cuda_bf16.h>
#include <math.h>
#include <stdint.h>

#define NV   50257
#define NPAD 50304          // 393 * 128
#define DD   128
#define BB_  2048
#define CC   10

// ---------------- scratch (static __device__ — allocation-free) ----------------
__device__ __align__(16) __nv_bfloat16 g_Wb[NPAD * DD];   // bf16 W_gen, zero-padded
__device__ float g_bgen[NPAD];                            // b_gen, -88 padded
__device__ __align__(16) __nv_bfloat16 g_zb[BB_ * DD];    // z in bf16
__device__ __align__(16) float g_zf[BB_ * DD];            // z in fp32
__device__ float g_S[BB_];                                // sum exp(logits) per row
__device__ float g_R[BB_];                                // sum of picked logits per row
__device__ float g_kl[BB_];

// ---------------- helpers ----------------
__device__ __forceinline__ float softplusf(float x) {
    return fmaxf(x, 0.f) + log1pf(expf(-fabsf(x)));
}

__device__ __forceinline__ void mma16816(float c[4], const uint32_t a[4],
                                         uint32_t b0, uint32_t b1) {
    asm volatile(
        "mma.sync.aligned.m16n8k16.row.col.f32.bf16.bf16.f32 "
        "{%0,%1,%2,%3},{%4,%5,%6,%7},{%8,%9},{%0,%1,%2,%3};\n"
        : "+f"(c[0]), "+f"(c[1]), "+f"(c[2]), "+f"(c[3])
        : "r"(a[0]), "r"(a[1]), "r"(a[2]), "r"(a[3]), "r"(b0), "r"(b1));
}

// ---------------- kernel 0: convert W_gen -> bf16, pad, zero accumulators ----------------
__global__ void k_convert(const float* __restrict__ W_gen,
                          const float* __restrict__ b_gen) {
    int gid = blockIdx.x * blockDim.x + threadIdx.x;
    int stride = gridDim.x * blockDim.x;
    for (int i = gid; i < NPAD * DD; i += stride)
        g_Wb[i] = __float2bfloat16(i < NV * DD ? W_gen[i] : 0.f);
    for (int i = gid; i < NPAD; i += stride)
        g_bgen[i] = (i < NV) ? b_gen[i] : -88.0f;
    for (int i = gid; i < BB_; i += stride) { g_S[i] = 0.f; g_R[i] = 0.f; }
}

// ---------------- kernel 1: inference network + KL + z ----------------
// 128 CTAs x 128 threads; each CTA handles 16 batch elements.
// SMEM: W_aff transposed [256][136] fp32, then reused for W_mu/W_sig transposed.
//       embeddings [16*11][128] fp32.
#define WT_LD 136
__global__ void __launch_bounds__(128) k_infnet(
    const int* __restrict__ x_batch, const int* __restrict__ ctx,
    const float* __restrict__ eps, const float* __restrict__ inf_emb,
    const float* __restrict__ W_aff, const float* __restrict__ b_aff,
    const float* __restrict__ W_mu,  const float* __restrict__ b_mu,
    const float* __restrict__ W_sig, const float* __restrict__ b_sig,
    const float* __restrict__ gen_sigma_emb)
{
    extern __shared__ float sm[];
    float* Wt   = sm;                       // 256*136 floats
    float* embs = sm + 256 * WT_LD;         // 176*128 floats

    const int tid  = threadIdx.x;
    const int w    = tid >> 5;
    const int lane = tid & 31;
    const int b0   = blockIdx.x * 16;

    // stage W_aff transposed: Wt[e][d] = W_aff[d][e]
    for (int idx = tid; idx < 128 * 256; idx += 128) {
        int d = idx >> 8, e = idx & 255;
        Wt[e * WT_LD + d] = W_aff[idx];
    }
    // stage embeddings: row r = b*11 + j ; j==0 -> center, else ctx[j-1]
    for (int r = w; r < 176; r += 4) {
        int b = r / 11, j = r - b * 11;
        int bg = b0 + b;
        int word = (j == 0) ? x_batch[bg] : ctx[bg * CC + (j - 1)];
        const float4* src = (const float4*)(inf_emb + (size_t)word * DD);
        ((float4*)(embs + r * 128))[lane] = src[lane];
    }
    __syncthreads();

    const int d0 = lane * 4;
    float4 ba = *(const float4*)(b_aff + d0);

    int bl[4];
    const float* cbase[4];
#pragma unroll
    for (int bb = 0; bb < 4; bb++) {
        bl[bb] = w + bb * 4;
        cbase[bb] = embs + (bl[bb] * 11) * 128;
    }

    // s0[bb][q] = b_aff + center . W_aff[:, 0:128]   (context-invariant part)
    float s0[4][4];
#pragma unroll
    for (int bb = 0; bb < 4; bb++) {
        s0[bb][0] = ba.x; s0[bb][1] = ba.y; s0[bb][2] = ba.z; s0[bb][3] = ba.w;
    }
#pragma unroll 4
    for (int e = 0; e < 128; e++) {
        float4 wv = *(const float4*)(Wt + e * WT_LD + d0);
#pragma unroll
        for (int bb = 0; bb < 4; bb++) {
            float cv = cbase[bb][e];
            s0[bb][0] += cv * wv.x; s0[bb][1] += cv * wv.y;
            s0[bb][2] += cv * wv.z; s0[bb][3] += cv * wv.w;
        }
    }

    float hsum[4][4];
#pragma unroll
    for (int bb = 0; bb < 4; bb++)
#pragma unroll
        for (int q = 0; q < 4; q++) hsum[bb][q] = 0.f;

    for (int c = 0; c < CC; c++) {
        float ha[4][4];
#pragma unroll
        for (int bb = 0; bb < 4; bb++)
#pragma unroll
            for (int q = 0; q < 4; q++) ha[bb][q] = s0[bb][q];
#pragma unroll 4
        for (int e = 0; e < 128; e++) {
            float4 wv = *(const float4*)(Wt + (128 + e) * WT_LD + d0);
#pragma unroll
            for (int bb = 0; bb < 4; bb++) {
                float cv = cbase[bb][(1 + c) * 128 + e];
                ha[bb][0] += cv * wv.x; ha[bb][1] += cv * wv.y;
                ha[bb][2] += cv * wv.z; ha[bb][3] += cv * wv.w;
            }
        }
#pragma unroll
        for (int bb = 0; bb < 4; bb++)
#pragma unroll
            for (int q = 0; q < 4; q++) hsum[bb][q] += fmaxf(ha[bb][q], 0.f);
    }

    __syncthreads();
    // reload: Wt rows [0:128) = W_mu^T, rows [128:256) = W_sig^T
    for (int idx = tid; idx < 128 * 128; idx += 128) {
        int d = idx >> 7, k = idx & 127;
        Wt[k * WT_LD + d]         = W_mu[idx];
        Wt[(128 + k) * WT_LD + d] = W_sig[idx];
    }
    __syncthreads();

    float4 bm = *(const float4*)(b_mu + d0);
    float4 bs = *(const float4*)(b_sig + d0);
    float mu[4][4], sg[4][4];
#pragma unroll
    for (int bb = 0; bb < 4; bb++) {
        mu[bb][0] = bm.x; mu[bb][1] = bm.y; mu[bb][2] = bm.z; mu[bb][3] = bm.w;
        sg[bb][0] = bs.x; sg[bb][1] = bs.y; sg[bb][2] = bs.z; sg[bb][3] = bs.w;
    }

    // GEMV: hs[k] lives at lane (k>>2), reg (k&3) within this warp
    for (int ll = 0; ll < 32; ll++) {
#pragma unroll
        for (int q = 0; q < 4; q++) {
            int k = ll * 4 + q;
            float4 wm4 = *(const float4*)(Wt + k * WT_LD + d0);
            float4 ws4 = *(const float4*)(Wt + (128 + k) * WT_LD + d0);
#pragma unroll
            for (int bb = 0; bb < 4; bb++) {
                float hv = __shfl_sync(0xffffffffu, hsum[bb][q], ll);
                mu[bb][0] += hv * wm4.x; mu[bb][1] += hv * wm4.y;
                mu[bb][2] += hv * wm4.z; mu[bb][3] += hv * wm4.w;
                sg[bb][0] += hv * ws4.x; sg[bb][1] += hv * ws4.y;
                sg[bb][2] += hv * ws4.z; sg[bb][3] += hv * ws4.w;
            }
        }
    }

    // epilogue: softplus, z, KL
#pragma unroll
    for (int bb = 0; bb < 4; bb++) {
        int bg = b0 + bl[bb];
        int xb = x_batch[bg];
        float4 ep4 = *(const float4*)(eps + (size_t)bg * DD + d0);
        float4 gs4 = *(const float4*)(gen_sigma_emb + (size_t)xb * DD + d0);
        float epv[4] = {ep4.x, ep4.y, ep4.z, ep4.w};
        float gsv[4] = {gs4.x, gs4.y, gs4.z, gs4.w};
        float zq[4];
        float klacc = 0.f;
#pragma unroll
        for (int q = 0; q < 4; q++) {
            float m   = mu[bb][q];
            float isg = softplusf(sg[bb][q]);
            float zv  = m + epv[q] * isg;
            zq[q] = zv;
            float sgm = softplusf(gsv[q]);
            float dm  = m - sgm;
            klacc += logf(sgm / isg)
                   + (isg * isg + dm * dm) / (2.f * sgm * sgm) - 0.5f;
        }
        *(float4*)(g_zf + (size_t)bg * DD + d0) = make_float4(zq[0], zq[1], zq[2], zq[3]);
        __nv_bfloat162 p0 = __floats2bfloat162_rn(zq[0], zq[1]);
        __nv_bfloat162 p1 = __floats2bfloat162_rn(zq[2], zq[3]);
        ((__nv_bfloat162*)(g_zb + (size_t)bg * DD + d0))[0] = p0;
        ((__nv_bfloat162*)(g_zb + (size_t)bg * DD + d0))[1] = p1;
#pragma unroll
        for (int o = 16; o; o >>= 1) klacc += __shfl_xor_sync(0xffffffffu, klacc, o);
        if (lane == 0) g_kl[bg] = klacc;
    }
}

// ---------------- kernel 2: bf16 MMA GEMM with exp-rowsum epilogue ----------------
// grid = 393 vocab tiles; each CTA keeps its W tile (128x128 bf16) in SMEM and
// loops over all 16 batch tiles, accumulating sum_n exp(logit + b_gen) into g_S.
#define TLD 136   // bf16 elems per smem row (128 + 8 pad -> conflict-free frags)
__global__ void __launch_bounds__(256) k_logits() {
    extern __shared__ __align__(16) char smraw[];
    __nv_bfloat16* As = (__nv_bfloat16*)smraw;             // 128*136
    __nv_bfloat16* Ws = As + 128 * TLD;                    // 128*136
    float* bg_s = (float*)(smraw + 2 * 128 * TLD * 2);     // 128 floats

    const int tid = threadIdx.x;
    const int v   = blockIdx.x;

    // 128 rows x 128 bf16 = 128 rows x 16 uint4  -> 2048 uint4 total
    for (int idx = tid; idx < 2048; idx += 256) {
        int r = idx >> 4, c = idx & 15;
        uint4 val = ((const uint4*)(g_Wb + ((size_t)(v * 128 + r)) * DD))[c];
        *(uint4*)(Ws + r * TLD + c * 8) = val;
    }
    if (tid < 128) bg_s[tid] = g_bgen[v * 128 + tid];

    const int w    = tid >> 5;
    const int lane = tid & 31;
    const int g    = lane >> 2;
    const int t    = lane & 3;
    const int wm   = w & 3;      // batch-row block of 32
    const int wn   = w >> 2;     // vocab-col block of 64

    for (int mt = 0; mt < 16; mt++) {
        __syncthreads();
        for (int idx = tid; idx < 2048; idx += 256) {
            int r = idx >> 4, c = idx & 15;
            uint4 val = ((const uint4*)(g_zb + ((size_t)(mt * 128 + r)) * DD))[c];
            *(uint4*)(As + r * TLD + c * 8) = val;
        }
        __syncthreads();

        float acc[2][8][4];
#pragma unroll
        for (int i = 0; i < 2; i++)
#pragma unroll
            for (int j = 0; j < 8; j++)
#pragma unroll
                for (int q = 0; q < 4; q++) acc[i][j][q] = 0.f;

#pragma unroll
        for (int kk = 0; kk < 8; kk++) {
            const int k0 = kk * 16;
            uint32_t a[2][4];
#pragma unroll
            for (int i = 0; i < 2; i++) {
                const __nv_bfloat16* base = As + (wm * 32 + i * 16 + g) * TLD + k0 + 2 * t;
                a[i][0] = *(const uint32_t*)base;
                a[i][1] = *(const uint32_t*)(base + 8 * TLD);
                a[i][2] = *(const uint32_t*)(base + 8);
                a[i][3] = *(const uint32_t*)(base + 8 * TLD + 8);
            }
#pragma unroll
            for (int j = 0; j < 8; j++) {
                const __nv_bfloat16* bp = Ws + (wn * 64 + j * 8 + g) * TLD + k0 + 2 * t;
                uint32_t b0 = *(const uint32_t*)bp;
                uint32_t b1 = *(const uint32_t*)(bp + 8);
                mma16816(acc[0][j], a[0], b0, b1);
                mma16816(acc[1][j], a[1], b0, b1);
            }
        }

        // epilogue: rowsum of exp(logit + b_gen)
#pragma unroll
        for (int i = 0; i < 2; i++) {
            float rs0 = 0.f, rs1 = 0.f;
#pragma unroll
            for (int j = 0; j < 8; j++) {
                int nl = wn * 64 + j * 8 + 2 * t;
                float bg0 = bg_s[nl], bg1 = bg_s[nl + 1];
                rs0 += __expf(acc[i][j][0] + bg0) + __expf(acc[i][j][1] + bg1);
                rs1 += __expf(acc[i][j][2] + bg0) + __expf(acc[i][j][3] + bg1);
            }
            rs0 += __shfl_xor_sync(0xffffffffu, rs0, 1);
            rs0 += __shfl_xor_sync(0xffffffffu, rs0, 2);
            rs1 += __shfl_xor_sync(0xffffffffu, rs1, 1);
            rs1 += __shfl_xor_sync(0xffffffffu, rs1, 2);
            if (t == 0) {
                int m = mt * 128 + wm * 32 + i * 16 + g;
                atomicAdd(&g_S[m], rs0);
                atomicAdd(&g_S[m + 8], rs1);
            }
        }
    }
}

// ---------------- kernel 3: picked context logits (fp32) ----------------
__global__ void __launch_bounds__(128) k_ctx(const int* __restrict__ ctx,
                                             const float* __restrict__ W_gen,
                                             const float* __restrict__ b_gen) {
    int w = threadIdx.x >> 5, lane = threadIdx.x & 31;
    int gw = blockIdx.x * 4 + w;              // 0..20479 = b*C + c
    int b = gw / CC;
    int n = ctx[gw];
    float4 z4 = ((const float4*)(g_zf + (size_t)b * DD))[lane];
    float4 w4 = ((const float4*)(W_gen + (size_t)n * DD))[lane];
    float d = z4.x * w4.x + z4.y * w4.y + z4.z * w4.z + z4.w * w4.w;
#pragma unroll
    for (int o = 16; o; o >>= 1) d += __shfl_xor_sync(0xffffffffu, d, o);
    if (lane == 0) atomicAdd(&g_R[b], d + b_gen[n]);
}

// ---------------- kernel 4: final reduction ----------------
__global__ void k_final(float* __restrict__ out) {
    __shared__ float red[256];
    float a = 0.f;
    for (int i = threadIdx.x; i < BB_; i += 256)
        a += g_kl[i] - g_R[i] + (float)CC * logf(g_S[i]);
    red[threadIdx.x] = a;
    __syncthreads();
    for (int s = 128; s; s >>= 1) {
        if (threadIdx.x < s) red[threadIdx.x] += red[threadIdx.x + s];
        __syncthreads();
    }
    if (threadIdx.x == 0) out[0] = red[0] / (float)BB_;
}

// ---------------- launch ----------------
extern "C" void kernel_launch(void* const* d_in, const int* in_sizes, int n_in,
                              void* d_out, int out_size) {
    const int*   x_batch = (const int*)  d_in[0];
    const int*   ctx     = (const int*)  d_in[1];
    const float* eps     = (const float*)d_in[2];
    const float* inf_emb = (const float*)d_in[3];
    const float* W_aff   = (const float*)d_in[4];
    const float* b_aff   = (const float*)d_in[5];
    const float* W_mu    = (const float*)d_in[6];
    const float* b_mu    = (const float*)d_in[7];
    const float* W_sig   = (const float*)d_in[8];
    const float* b_sig   = (const float*)d_in[9];
    const float* gse     = (const float*)d_in[10];
    const float* W_gen   = (const float*)d_in[11];
    const float* b_gen   = (const float*)d_in[12];

    const int SMEM_A = (256 * WT_LD + 176 * 128) * 4;          // 229376 B
    const int SMEM_B = 2 * 128 * TLD * 2 + 128 * 4;            // 70144 B
    cudaFuncSetAttribute(k_infnet, cudaFuncAttributeMaxDynamicSharedMemorySize, SMEM_A);
    cudaFuncSetAttribute(k_logits, cudaFuncAttributeMaxDynamicSharedMemorySize, SMEM_B);

    k_convert<<<256, 256>>>(W_gen, b_gen);
    k_infnet<<<128, 128, SMEM_A>>>(x_batch, ctx, eps, inf_emb, W_aff, b_aff,
                                   W_mu, b_mu, W_sig, b_sig, gse);
    k_logits<<<NPAD / 128, 256, SMEM_B>>>();
    k_ctx<<<(BB_ * CC) / 4, 128>>>(ctx, W_gen, b_gen);
    k_final<<<1, 256>>>((float*)d_out);
}

// round 4
// speedup vs baseline: 1.4511x; 1.4511x over previous
#include <cuda_runtime.h>
#include <cuda_bf16.h>
#include <math.h>
#include <stdint.h>

#define NV   50257
#define NPAD 50304          // 393 * 128
#define DD   128
#define BB_  2048
#define CC   10

// Does THIS compilation pass support tcgen05? (sm_103a / sm_100a arch-specific,
// or sm_1xxf family-specific). Plain sm_103 pass compiles the mma.sync fallback.
#if defined(__CUDA_ARCH__) && (defined(__CUDA_ARCH_FEAT_SM103_ALL) || \
    defined(__CUDA_ARCH_FEAT_SM100_ALL) || defined(__CUDA_ARCH_FAMILY_SPECIFIC__))
#define HAS_TCGEN05 1
#else
#define HAS_TCGEN05 0
#endif

// ---------------- scratch (static __device__ — allocation-free) ----------------
__device__ __align__(16) __nv_bfloat16 g_zb[BB_ * DD];    // z in bf16
__device__ __align__(16) float g_zf[BB_ * DD];            // z in fp32
__device__ float g_S[BB_];                                // sum exp(logits) per row
__device__ float g_R[BB_];                                // sum of picked logits per row
__device__ float g_kl[BB_];

// ---------------- common helpers ----------------
__device__ __forceinline__ uint32_t smem_to_u32(const void* p) {
    uint32_t a;
    asm("{ .reg .u64 t; cvta.to.shared.u64 t, %1; cvt.u32.u64 %0, t; }"
        : "=r"(a) : "l"(p));
    return a;
}
__device__ __forceinline__ float softplusf(float x) {
    return fmaxf(x, 0.f) + log1pf(expf(-fabsf(x)));
}

// ---------------- kernel 1: inference network + KL + z ----------------
#define WT_LD 136
__global__ void __launch_bounds__(128) k_infnet(
    const int* __restrict__ x_batch, const int* __restrict__ ctx,
    const float* __restrict__ eps, const float* __restrict__ inf_emb,
    const float* __restrict__ W_aff, const float* __restrict__ b_aff,
    const float* __restrict__ W_mu,  const float* __restrict__ b_mu,
    const float* __restrict__ W_sig, const float* __restrict__ b_sig,
    const float* __restrict__ gen_sigma_emb)
{
    extern __shared__ float sm[];
    float* Wt   = sm;                       // 256*136 floats
    float* embs = sm + 256 * WT_LD;         // 176*128 floats

    const int tid  = threadIdx.x;
    const int w    = tid >> 5;
    const int lane = tid & 31;
    const int b0   = blockIdx.x * 16;

    if (tid < 16) { g_S[b0 + tid] = 0.f; g_R[b0 + tid] = 0.f; }

    for (int idx = tid; idx < 128 * 256; idx += 128) {
        int d = idx >> 8, e = idx & 255;
        Wt[e * WT_LD + d] = W_aff[idx];
    }
    for (int r = w; r < 176; r += 4) {
        int b = r / 11, j = r - b * 11;
        int bg = b0 + b;
        int word = (j == 0) ? x_batch[bg] : ctx[bg * CC + (j - 1)];
        const float4* src = (const float4*)(inf_emb + (size_t)word * DD);
        ((float4*)(embs + r * 128))[lane] = src[lane];
    }
    __syncthreads();

    const int d0 = lane * 4;
    float4 ba = *(const float4*)(b_aff + d0);

    int bl[4];
    const float* cbase[4];
#pragma unroll
    for (int bb = 0; bb < 4; bb++) {
        bl[bb] = w + bb * 4;
        cbase[bb] = embs + (bl[bb] * 11) * 128;
    }

    float s0[4][4];
#pragma unroll
    for (int bb = 0; bb < 4; bb++) {
        s0[bb][0] = ba.x; s0[bb][1] = ba.y; s0[bb][2] = ba.z; s0[bb][3] = ba.w;
    }
#pragma unroll 4
    for (int e = 0; e < 128; e++) {
        float4 wv = *(const float4*)(Wt + e * WT_LD + d0);
#pragma unroll
        for (int bb = 0; bb < 4; bb++) {
            float cv = cbase[bb][e];
            s0[bb][0] += cv * wv.x; s0[bb][1] += cv * wv.y;
            s0[bb][2] += cv * wv.z; s0[bb][3] += cv * wv.w;
        }
    }

    float hsum[4][4];
#pragma unroll
    for (int bb = 0; bb < 4; bb++)
#pragma unroll
        for (int q = 0; q < 4; q++) hsum[bb][q] = 0.f;

    for (int c = 0; c < CC; c++) {
        float ha[4][4];
#pragma unroll
        for (int bb = 0; bb < 4; bb++)
#pragma unroll
            for (int q = 0; q < 4; q++) ha[bb][q] = s0[bb][q];
#pragma unroll 4
        for (int e = 0; e < 128; e++) {
            float4 wv = *(const float4*)(Wt + (128 + e) * WT_LD + d0);
#pragma unroll
            for (int bb = 0; bb < 4; bb++) {
                float cv = cbase[bb][(1 + c) * 128 + e];
                ha[bb][0] += cv * wv.x; ha[bb][1] += cv * wv.y;
                ha[bb][2] += cv * wv.z; ha[bb][3] += cv * wv.w;
            }
        }
#pragma unroll
        for (int bb = 0; bb < 4; bb++)
#pragma unroll
            for (int q = 0; q < 4; q++) hsum[bb][q] += fmaxf(ha[bb][q], 0.f);
    }

    __syncthreads();
    for (int idx = tid; idx < 128 * 128; idx += 128) {
        int d = idx >> 7, k = idx & 127;
        Wt[k * WT_LD + d]         = W_mu[idx];
        Wt[(128 + k) * WT_LD + d] = W_sig[idx];
    }
    __syncthreads();

    float4 bm = *(const float4*)(b_mu + d0);
    float4 bs = *(const float4*)(b_sig + d0);
    float mu[4][4], sg[4][4];
#pragma unroll
    for (int bb = 0; bb < 4; bb++) {
        mu[bb][0] = bm.x; mu[bb][1] = bm.y; mu[bb][2] = bm.z; mu[bb][3] = bm.w;
        sg[bb][0] = bs.x; sg[bb][1] = bs.y; sg[bb][2] = bs.z; sg[bb][3] = bs.w;
    }

    for (int ll = 0; ll < 32; ll++) {
#pragma unroll
        for (int q = 0; q < 4; q++) {
            int k = ll * 4 + q;
            float4 wm4 = *(const float4*)(Wt + k * WT_LD + d0);
            float4 ws4 = *(const float4*)(Wt + (128 + k) * WT_LD + d0);
#pragma unroll
            for (int bb = 0; bb < 4; bb++) {
                float hv = __shfl_sync(0xffffffffu, hsum[bb][q], ll);
                mu[bb][0] += hv * wm4.x; mu[bb][1] += hv * wm4.y;
                mu[bb][2] += hv * wm4.z; mu[bb][3] += hv * wm4.w;
                sg[bb][0] += hv * ws4.x; sg[bb][1] += hv * ws4.y;
                sg[bb][2] += hv * ws4.z; sg[bb][3] += hv * ws4.w;
            }
        }
    }

#pragma unroll
    for (int bb = 0; bb < 4; bb++) {
        int bg = b0 + bl[bb];
        int xb = x_batch[bg];
        float4 ep4 = *(const float4*)(eps + (size_t)bg * DD + d0);
        float4 gs4 = *(const float4*)(gen_sigma_emb + (size_t)xb * DD + d0);
        float epv[4] = {ep4.x, ep4.y, ep4.z, ep4.w};
        float gsv[4] = {gs4.x, gs4.y, gs4.z, gs4.w};
        float zq[4];
        float klacc = 0.f;
#pragma unroll
        for (int q = 0; q < 4; q++) {
            float m   = mu[bb][q];
            float isg = softplusf(sg[bb][q]);
            float zv  = m + epv[q] * isg;
            zq[q] = zv;
            float sgm = softplusf(gsv[q]);
            float dm  = m - sgm;
            klacc += logf(sgm / isg)
                   + (isg * isg + dm * dm) / (2.f * sgm * sgm) - 0.5f;
        }
        *(float4*)(g_zf + (size_t)bg * DD + d0) = make_float4(zq[0], zq[1], zq[2], zq[3]);
        __nv_bfloat162 p0 = __floats2bfloat162_rn(zq[0], zq[1]);
        __nv_bfloat162 p1 = __floats2bfloat162_rn(zq[2], zq[3]);
        ((__nv_bfloat162*)(g_zb + (size_t)bg * DD + d0))[0] = p0;
        ((__nv_bfloat162*)(g_zb + (size_t)bg * DD + d0))[1] = p1;
#pragma unroll
        for (int o = 16; o; o >>= 1) klacc += __shfl_xor_sync(0xffffffffu, klacc, o);
        if (lane == 0) g_kl[bg] = klacc;
    }
}

// ======================== k_logits: two arch paths ========================

#if HAS_TCGEN05
// ---- tcgen05 helpers (only in 'a'/'f' passes) ----
__device__ __forceinline__ uint32_t elect_one_pred() {
    uint32_t pred;
    asm volatile(
        "{\n\t.reg .pred p;\n\t"
        "elect.sync _|p, 0xFFFFFFFF;\n\t"
        "selp.b32 %0, 1, 0, p;\n\t}"
        : "=r"(pred));
    return pred;
}
#define MBARRIER_INIT(mbar, cnt) \
    asm volatile("mbarrier.init.shared.b64 [%0], %1;" :: "r"((uint32_t)(mbar)), "r"((uint32_t)(cnt)) : "memory")
#define MBARRIER_WAIT_PARITY(mbar, par) do { \
    uint32_t _m = (uint32_t)(mbar); uint32_t _p = (uint32_t)(par); uint32_t _d; \
    asm volatile("{\n\t.reg .pred p;\n\t" \
        "mbarrier.try_wait.parity.acquire.cta.shared::cta.b64 p, [%1], %2;\n\t" \
        "selp.b32 %0, 1, 0, p;\n\t}" : "=r"(_d) : "r"(_m), "r"(_p) : "memory"); \
    if (!_d) { \
        asm volatile("{\n\t.reg .pred P1;\n\t" \
            "WL_%=:\n\t" \
            "mbarrier.try_wait.parity.acquire.cta.shared::cta.b64 P1, [%0], %1, 0x989680;\n\t" \
            "@P1 bra.uni WD_%=;\n\t" \
            "bra.uni WL_%=;\n\t" \
            "WD_%=:\n\t}" :: "r"(_m), "r"(_p) : "memory"); \
    } } while (0)
#define TCGEN05_ALLOC(smem_addr, nCols) \
    asm volatile("tcgen05.alloc.cta_group::1.sync.aligned.shared::cta.b32 [%0], %1;" \
        :: "r"((uint32_t)(smem_addr)), "r"((uint32_t)(nCols)) : "memory")
#define TCGEN05_DEALLOC(tmem, nCols) \
    asm volatile("tcgen05.dealloc.cta_group::1.sync.aligned.b32 %0, %1;" :: "r"(tmem), "r"((uint32_t)(nCols)))
#define TCGEN05_RELINQUISH() \
    asm volatile("tcgen05.relinquish_alloc_permit.cta_group::1.sync.aligned;")
#define TCGEN05_COMMIT(mbar) \
    asm volatile("tcgen05.commit.cta_group::1.mbarrier::arrive::one.shared::cluster.b64 [%0];" \
        :: "r"((uint32_t)(mbar)) : "memory")
#define TCGEN05_FENCE_BEFORE() asm volatile("tcgen05.fence::before_thread_sync;" ::: "memory")
#define TCGEN05_FENCE_AFTER()  asm volatile("tcgen05.fence::after_thread_sync;" ::: "memory")
#define TCGEN05_WAIT_LD()      asm volatile("tcgen05.wait::ld.sync.aligned;" ::: "memory")
#define FENCE_PROXY_ASYNC()    asm volatile("fence.proxy.async.shared::cta;" ::: "memory")
#define TCGEN05_LD_32X32B_X32(r, tmem_addr) \
    asm volatile( \
        "tcgen05.ld.sync.aligned.32x32b.x32.b32 " \
        "{%0, %1, %2, %3, %4, %5, %6, %7, " \
        " %8, %9, %10, %11, %12, %13, %14, %15, " \
        " %16, %17, %18, %19, %20, %21, %22, %23, " \
        " %24, %25, %26, %27, %28, %29, %30, %31}, [%32];" \
        : "=r"((r)[0]),  "=r"((r)[1]),  "=r"((r)[2]),  "=r"((r)[3]), \
          "=r"((r)[4]),  "=r"((r)[5]),  "=r"((r)[6]),  "=r"((r)[7]), \
          "=r"((r)[8]),  "=r"((r)[9]),  "=r"((r)[10]), "=r"((r)[11]), \
          "=r"((r)[12]), "=r"((r)[13]), "=r"((r)[14]), "=r"((r)[15]), \
          "=r"((r)[16]), "=r"((r)[17]), "=r"((r)[18]), "=r"((r)[19]), \
          "=r"((r)[20]), "=r"((r)[21]), "=r"((r)[22]), "=r"((r)[23]), \
          "=r"((r)[24]), "=r"((r)[25]), "=r"((r)[26]), "=r"((r)[27]), \
          "=r"((r)[28]), "=r"((r)[29]), "=r"((r)[30]), "=r"((r)[31]) \
        : "r"(tmem_addr))
static constexpr uint64_t SMEM_DESC_BASE_SW128 =
    (uint64_t(2) << 61) | (uint64_t(1) << 46) | (uint64_t(64) << 32) | (uint64_t(1) << 16);
#define MAKE_SMEM_DESC(addr) (SMEM_DESC_BASE_SW128 | ((uint64_t)((addr) >> 4) & 0x3FFF))
#define IDESC_LOG 0x08200490u   // f32 accum, bf16 x bf16, M=128, N=128

__device__ __forceinline__ void mma_f16_ss(uint32_t d_tmem, uint64_t a_desc,
                                           uint64_t b_desc, uint32_t idesc, bool accum) {
    uint32_t en = accum ? 1u : 0u;
    asm volatile(
        "{\n\t.reg .pred p;\n\t"
        "setp.ne.u32 p, %4, 0;\n\t"
        "tcgen05.mma.cta_group::1.kind::f16 [%0], %1, %2, %3, {%5,%5,%5,%5}, p;\n\t}"
        :: "r"(d_tmem), "l"(a_desc), "l"(b_desc), "r"(idesc), "r"(en), "r"(0u)
        : "memory");
}

#define SM_TPTR  0
#define SM_MBAR0 8
#define SM_MBAR1 16
#define SM_BG    32
#define SM_W     1024
#define SM_Z0    (1024 + 32768)
#define SM_Z1    (1024 + 65536)

__device__ __forceinline__ void logits_epilogue(int me, uint32_t sb, uint32_t tmem,
                                                const float* bg_s, int w, int lane) {
    const int q = me & 1;
    MBARRIER_WAIT_PARITY(sb + (q ? SM_MBAR1 : SM_MBAR0), (me >> 1) & 1);
    TCGEN05_FENCE_AFTER();
    const uint32_t woff = ((uint32_t)(w & 3)) << 21;
    const int cb = (w < 4) ? 0 : 64;
    const uint32_t dt = tmem + (uint32_t)(q * 128 + cb) + woff;
    uint32_t r0[32], r1[32];
    TCGEN05_LD_32X32B_X32(r0, dt);
    TCGEN05_LD_32X32B_X32(r1, dt + 32);
    TCGEN05_WAIT_LD();
    TCGEN05_FENCE_BEFORE();
    float acc = 0.f;
#pragma unroll
    for (int c = 0; c < 32; c++) acc += __expf(__uint_as_float(r0[c]) + bg_s[cb + c]);
#pragma unroll
    for (int c = 0; c < 32; c++) acc += __expf(__uint_as_float(r1[c]) + bg_s[cb + 32 + c]);
    atomicAdd(&g_S[me * 128 + (w & 3) * 32 + lane], acc);
}
#endif  // HAS_TCGEN05

// ---- fallback helpers (baseline sm_103: mma.sync + cp.async) ----
__device__ __forceinline__ void mma16816(float c[4], const uint32_t a[4],
                                         uint32_t b0, uint32_t b1) {
    asm volatile(
        "mma.sync.aligned.m16n8k16.row.col.f32.bf16.bf16.f32 "
        "{%0,%1,%2,%3},{%4,%5,%6,%7},{%8,%9},{%0,%1,%2,%3};\n"
        : "+f"(c[0]), "+f"(c[1]), "+f"(c[2]), "+f"(c[3])
        : "r"(a[0]), "r"(a[1]), "r"(a[2]), "r"(a[3]), "r"(b0), "r"(b1));
}
#define CP_ASYNC16(dst, src) \
    asm volatile("cp.async.cg.shared.global [%0], [%1], 16;" :: "r"(dst), "l"(src))
#define CP_COMMIT()  asm volatile("cp.async.commit_group;" ::: "memory")
#define CP_WAIT(n)   asm volatile("cp.async.wait_group %0;" :: "n"(n) : "memory")

#define TLD    136
#define FB_AS0 0
#define FB_AS1 34816
#define FB_WS  69632
#define FB_BG  104448
#define SMEM_LOG 104960   // covers both paths (tcgen05 path needs 99328)

__device__ __forceinline__ void fb_prefetch(uint32_t sb, int mt, int p, int tid) {
#pragma unroll
    for (int idx = tid; idx < 2048; idx += 256) {
        int r = idx >> 4, c = idx & 15;
        uint32_t dst = sb + (uint32_t)(p * 34816 + (r * TLD + c * 8) * 2);
        const void* src = (const void*)(g_zb + (size_t)(mt * 128 + r) * DD + c * 8);
        CP_ASYNC16(dst, src);
    }
    CP_COMMIT();
}

__global__ void __launch_bounds__(256, 2) k_logits(const float* __restrict__ W_gen,
                                                   const float* __restrict__ b_gen) {
#if HAS_TCGEN05
    // ---------------- tcgen05 path ----------------
    extern __shared__ __align__(16) char smem[];
    const uint32_t sb = smem_to_u32(smem);
    const int tid  = threadIdx.x;
    const int w    = tid >> 5;
    const int lane = tid & 31;
    const int n0   = blockIdx.x * 128;

    if (w == 0) { TCGEN05_ALLOC(sb + SM_TPTR, 256); TCGEN05_RELINQUISH(); }
    if (tid == 0) { MBARRIER_INIT(sb + SM_MBAR0, 1); MBARRIER_INIT(sb + SM_MBAR1, 1); }

    // stationary W tile: fp32 -> bf16, SW128-swizzled halves (k0..63 | k64..127)
    for (int gidx = tid; gidx < 2048; gidx += 256) {
        int r  = gidx >> 4;
        int g8 = gidx & 15;
        int n  = n0 + r;
        uint4 outv = make_uint4(0u, 0u, 0u, 0u);
        if (n < NV) {
            const float4* src = (const float4*)(W_gen + (size_t)n * DD + g8 * 8);
            float4 f0 = src[0], f1 = src[1];
            __nv_bfloat162 h0 = __floats2bfloat162_rn(f0.x, f0.y);
            __nv_bfloat162 h1 = __floats2bfloat162_rn(f0.z, f0.w);
            __nv_bfloat162 h2 = __floats2bfloat162_rn(f1.x, f1.y);
            __nv_bfloat162 h3 = __floats2bfloat162_rn(f1.z, f1.w);
            outv.x = *(uint32_t*)&h0; outv.y = *(uint32_t*)&h1;
            outv.z = *(uint32_t*)&h2; outv.w = *(uint32_t*)&h3;
        }
        int half = g8 >> 3;
        uint32_t boff = (uint32_t)(r * 128 + (g8 & 7) * 16);
        uint32_t sw = boff ^ ((boff >> 3) & 0x70);
        *(uint4*)(smem + SM_W + half * 16384 + sw) = outv;
    }
    if (tid < 128) {
        int n = n0 + tid;
        ((float*)(smem + SM_BG))[tid] = (n < NV) ? b_gen[n] : -88.0f;
    }
    FENCE_PROXY_ASYNC();
    __syncthreads();

    uint32_t tmem;
    asm volatile("ld.shared.b32 %0, [%1];" : "=r"(tmem) : "r"(sb + SM_TPTR));
    const float* bg_s = (const float*)(smem + SM_BG);

    const uint64_t bd0 = MAKE_SMEM_DESC(sb + SM_W);
    const uint64_t bd1 = MAKE_SMEM_DESC(sb + SM_W + 16384);

    for (int mt = 0; mt < 16; mt++) {
        const int p = mt & 1, k = mt >> 1;
        const uint32_t zoff = p ? SM_Z1 : SM_Z0;
        if (mt >= 2) MBARRIER_WAIT_PARITY(sb + (p ? SM_MBAR1 : SM_MBAR0), (k - 1) & 1);
        for (int gidx = tid; gidx < 2048; gidx += 256) {
            int r = gidx >> 4, g8 = gidx & 15;
            uint4 val = *(const uint4*)(g_zb + ((size_t)(mt * 128 + r)) * DD + g8 * 8);
            int half = g8 >> 3;
            uint32_t boff = (uint32_t)(r * 128 + (g8 & 7) * 16);
            uint32_t sw = boff ^ ((boff >> 3) & 0x70);
            *(uint4*)(smem + zoff + half * 16384 + sw) = val;
        }
        FENCE_PROXY_ASYNC();
        __syncthreads();
        if (w == 0) {
            TCGEN05_FENCE_AFTER();
            if (elect_one_pred()) {
                const uint64_t ad0 = MAKE_SMEM_DESC(sb + zoff);
                const uint64_t ad1 = MAKE_SMEM_DESC(sb + zoff + 16384);
                const uint32_t dt = tmem + (uint32_t)(p * 128);
#pragma unroll
                for (int s = 0; s < 8; s++) {
                    uint64_t ad = ((s >> 2) ? ad1 : ad0) + (uint64_t)((s & 3) * 2);
                    uint64_t bd = ((s >> 2) ? bd1 : bd0) + (uint64_t)((s & 3) * 2);
                    mma_f16_ss(dt, ad, bd, IDESC_LOG, s > 0);
                }
                TCGEN05_COMMIT(sb + (p ? SM_MBAR1 : SM_MBAR0));
            }
        }
        if (mt >= 1) logits_epilogue(mt - 1, sb, tmem, bg_s, w, lane);
    }
    logits_epilogue(15, sb, tmem, bg_s, w, lane);
    __syncthreads();
    if (w == 0) TCGEN05_DEALLOC(tmem, 256);
#else
    // ---------------- fallback: mma.sync + cp.async double buffer ----------------
    extern __shared__ __align__(16) char smem[];
    const uint32_t sb = smem_to_u32(smem);
    __nv_bfloat16* Ws = (__nv_bfloat16*)(smem + FB_WS);
    float* bg_s = (float*)(smem + FB_BG);

    const int tid = threadIdx.x;
    const int n0  = blockIdx.x * 128;

    // stage W tile: fp32 -> bf16, padded rows, TLD layout
    for (int gidx = tid; gidx < 2048; gidx += 256) {
        int r = gidx >> 4, c = gidx & 15;
        int n = n0 + r;
        uint4 outv = make_uint4(0u, 0u, 0u, 0u);
        if (n < NV) {
            const float4* src = (const float4*)(W_gen + (size_t)n * DD + c * 8);
            float4 f0 = src[0], f1 = src[1];
            __nv_bfloat162 h0 = __floats2bfloat162_rn(f0.x, f0.y);
            __nv_bfloat162 h1 = __floats2bfloat162_rn(f0.z, f0.w);
            __nv_bfloat162 h2 = __floats2bfloat162_rn(f1.x, f1.y);
            __nv_bfloat162 h3 = __floats2bfloat162_rn(f1.z, f1.w);
            outv.x = *(uint32_t*)&h0; outv.y = *(uint32_t*)&h1;
            outv.z = *(uint32_t*)&h2; outv.w = *(uint32_t*)&h3;
        }
        *(uint4*)(Ws + r * TLD + c * 8) = outv;
    }
    if (tid < 128) {
        int n = n0 + tid;
        bg_s[tid] = (n < NV) ? b_gen[n] : -88.0f;
    }

    const int w    = tid >> 5;
    const int lane = tid & 31;
    const int g    = lane >> 2;
    const int t    = lane & 3;
    const int wm   = w & 3;
    const int wn   = w >> 2;

    fb_prefetch(sb, 0, 0, tid);

    for (int mt = 0; mt < 16; mt++) {
        const int p = mt & 1;
        if (mt + 1 < 16) { fb_prefetch(sb, mt + 1, p ^ 1, tid); CP_WAIT(1); }
        else             { CP_WAIT(0); }
        __syncthreads();
        const __nv_bfloat16* As = (const __nv_bfloat16*)(smem + p * 34816);

        float acc[2][8][4];
#pragma unroll
        for (int i = 0; i < 2; i++)
#pragma unroll
            for (int j = 0; j < 8; j++)
#pragma unroll
                for (int q = 0; q < 4; q++) acc[i][j][q] = 0.f;

#pragma unroll
        for (int kk = 0; kk < 8; kk++) {
            const int k0 = kk * 16;
            uint32_t a[2][4];
#pragma unroll
            for (int i = 0; i < 2; i++) {
                const __nv_bfloat16* base = As + (wm * 32 + i * 16 + g) * TLD + k0 + 2 * t;
                a[i][0] = *(const uint32_t*)base;
                a[i][1] = *(const uint32_t*)(base + 8 * TLD);
                a[i][2] = *(const uint32_t*)(base + 8);
                a[i][3] = *(const uint32_t*)(base + 8 * TLD + 8);
            }
#pragma unroll
            for (int j = 0; j < 8; j++) {
                const __nv_bfloat16* bp = Ws + (wn * 64 + j * 8 + g) * TLD + k0 + 2 * t;
                uint32_t b0 = *(const uint32_t*)bp;
                uint32_t b1 = *(const uint32_t*)(bp + 8);
                mma16816(acc[0][j], a[0], b0, b1);
                mma16816(acc[1][j], a[1], b0, b1);
            }
        }

#pragma unroll
        for (int i = 0; i < 2; i++) {
            float rs0 = 0.f, rs1 = 0.f;
#pragma unroll
            for (int j = 0; j < 8; j++) {
                int nl = wn * 64 + j * 8 + 2 * t;
                float bg0 = bg_s[nl], bg1 = bg_s[nl + 1];
                rs0 += __expf(acc[i][j][0] + bg0) + __expf(acc[i][j][1] + bg1);
                rs1 += __expf(acc[i][j][2] + bg0) + __expf(acc[i][j][3] + bg1);
            }
            rs0 += __shfl_xor_sync(0xffffffffu, rs0, 1);
            rs0 += __shfl_xor_sync(0xffffffffu, rs0, 2);
            rs1 += __shfl_xor_sync(0xffffffffu, rs1, 1);
            rs1 += __shfl_xor_sync(0xffffffffu, rs1, 2);
            if (t == 0) {
                int m = mt * 128 + wm * 32 + i * 16 + g;
                atomicAdd(&g_S[m], rs0);
                atomicAdd(&g_S[m + 8], rs1);
            }
        }
        __syncthreads();
    }
#endif
}

// ---------------- kernel 3: picked context logits (fp32, 4 pairs/warp) ----------------
__global__ void __launch_bounds__(128) k_ctx(const int* __restrict__ ctx,
                                             const float* __restrict__ W_gen,
                                             const float* __restrict__ b_gen) {
    int w = threadIdx.x >> 5, lane = threadIdx.x & 31;
    int base = (blockIdx.x * 4 + w) * 4;
    int bq[4], nq[4];
#pragma unroll
    for (int it = 0; it < 4; it++) {
        int gw = base + it;
        bq[it] = gw / CC;
        nq[it] = ctx[gw];
    }
    float4 zc[4], wc[4];
#pragma unroll
    for (int it = 0; it < 4; it++) {
        zc[it] = ((const float4*)(g_zf + (size_t)bq[it] * DD))[lane];
        wc[it] = ((const float4*)(W_gen + (size_t)nq[it] * DD))[lane];
    }
#pragma unroll
    for (int it = 0; it < 4; it++) {
        float d = zc[it].x * wc[it].x + zc[it].y * wc[it].y
                + zc[it].z * wc[it].z + zc[it].w * wc[it].w;
#pragma unroll
        for (int o = 16; o; o >>= 1) d += __shfl_xor_sync(0xffffffffu, d, o);
        if (lane == 0) atomicAdd(&g_R[bq[it]], d + b_gen[nq[it]]);
    }
}

// ---------------- kernel 4: final reduction ----------------
__global__ void k_final(float* __restrict__ out) {
    __shared__ float red[256];
    float a = 0.f;
    for (int i = threadIdx.x; i < BB_; i += 256)
        a += g_kl[i] - g_R[i] + (float)CC * logf(g_S[i]);
    red[threadIdx.x] = a;
    __syncthreads();
    for (int s = 128; s; s >>= 1) {
        if (threadIdx.x < s) red[threadIdx.x] += red[threadIdx.x + s];
        __syncthreads();
    }
    if (threadIdx.x == 0) out[0] = red[0] / (float)BB_;
}

// ---------------- launch ----------------
extern "C" void kernel_launch(void* const* d_in, const int* in_sizes, int n_in,
                              void* d_out, int out_size) {
    const int*   x_batch = (const int*)  d_in[0];
    const int*   ctx     = (const int*)  d_in[1];
    const float* eps     = (const float*)d_in[2];
    const float* inf_emb = (const float*)d_in[3];
    const float* W_aff   = (const float*)d_in[4];
    const float* b_aff   = (const float*)d_in[5];
    const float* W_mu    = (const float*)d_in[6];
    const float* b_mu    = (const float*)d_in[7];
    const float* W_sig   = (const float*)d_in[8];
    const float* b_sig   = (const float*)d_in[9];
    const float* gse     = (const float*)d_in[10];
    const float* W_gen   = (const float*)d_in[11];
    const float* b_gen   = (const float*)d_in[12];

    const int SMEM_A = (256 * WT_LD + 176 * 128) * 4;   // 229376 B
    cudaFuncSetAttribute(k_infnet, cudaFuncAttributeMaxDynamicSharedMemorySize, SMEM_A);
    cudaFuncSetAttribute(k_logits, cudaFuncAttributeMaxDynamicSharedMemorySize, SMEM_LOG);

    k_infnet<<<128, 128, SMEM_A>>>(x_batch, ctx, eps, inf_emb, W_aff, b_aff,
                                   W_mu, b_mu, W_sig, b_sig, gse);
    k_logits<<<NPAD / 128, 256, SMEM_LOG>>>(W_gen, b_gen);
    k_ctx<<<(BB_ * CC) / 16, 128>>>(ctx, W_gen, b_gen);
    k_final<<<1, 256>>>((float*)d_out);
}